// round 2
// baseline (speedup 1.0000x reference)
#include <cuda_runtime.h>
#include <math.h>
#include <stddef.h>

// Problem constants
#define BB   2
#define LL   2048
#define DD   2048
#define HH   16
#define HDD  128
#define FF_  8192
#define RR   4096          // B*L
#define QKVD 6144          // 3*D
#define NEGV (-1000000000.0f)

// ---------------------------------------------------------------------------
// Scratch (allocation-free: __device__ globals)
// ---------------------------------------------------------------------------
__device__ float g_h1[(size_t)RR * DD];        // rmsnorm1 output
__device__ float g_qkv[(size_t)RR * QKVD];     // qkv projections
__device__ float g_scores[(size_t)BB * HH * LL * LL]; // attention scores / probs
__device__ float g_o[(size_t)RR * DD];         // attention output (b,l,h,d)
__device__ float g_x2[(size_t)RR * DD];        // x + attn out-proj
__device__ float g_h2[(size_t)RR * DD];        // rmsnorm2 output
__device__ float g_gate[(size_t)RR * FF_];     // gate proj (then silu*up in place)
__device__ float g_up[(size_t)RR * FF_];       // up proj

// ---------------------------------------------------------------------------
// RMSNorm: one block per row, 256 threads, D=2048
// ---------------------------------------------------------------------------
__global__ void __launch_bounds__(256) rmsnorm_kernel(
    const float* __restrict__ x, const float* __restrict__ w,
    float* __restrict__ out)
{
    int row = blockIdx.x;
    int tid = threadIdx.x;
    const float* xr = x + (size_t)row * DD;
    float v[8];
    float s = 0.f;
#pragma unroll
    for (int i = 0; i < 8; i++) {
        v[i] = xr[tid + i * 256];
        s += v[i] * v[i];
    }
    __shared__ float red[256];
    red[tid] = s;
    __syncthreads();
    for (int o = 128; o > 0; o >>= 1) {
        if (tid < o) red[tid] += red[tid + o];
        __syncthreads();
    }
    float rs = rsqrtf(red[0] / (float)DD + 1e-6f);
    float* orow = out + (size_t)row * DD;
#pragma unroll
    for (int i = 0; i < 8; i++) {
        int c = tid + i * 256;
        orow[c] = v[i] * rs * w[c];
    }
}

// ---------------------------------------------------------------------------
// Generic NT GEMM: C[M,N] = A[M,K] @ B[N,K]^T  (+ residual if EPI==1)
// BM=BN=128, BK=16, 256 threads, 8x8 per thread.
// Requires M%128==0, N%128==0, K%16==0 (true for all uses here).
// ---------------------------------------------------------------------------
template <int EPI>
__global__ void __launch_bounds__(256) gemm_nt(
    const float* __restrict__ A, const float* __restrict__ Bm,
    const float* __restrict__ Rsd, float* __restrict__ C,
    int M, int N, int K)
{
    __shared__ float As[16][128];
    __shared__ float Bs[16][128];
    int tid = threadIdx.x;
    int bx = blockIdx.x, by = blockIdx.y;
    int ty = tid >> 4, tx = tid & 15;

    float acc[8][8];
#pragma unroll
    for (int i = 0; i < 8; i++)
#pragma unroll
        for (int j = 0; j < 8; j++) acc[i][j] = 0.f;

    const float* Ablk = A + (size_t)by * 128 * K;
    const float* Bblk = Bm + (size_t)bx * 128 * K;

    for (int k0 = 0; k0 < K; k0 += 16) {
#pragma unroll
        for (int t = 0; t < 2; t++) {
            int id = tid + t * 256;          // 0..511
            int row = id >> 2;               // 0..127
            int kq = (id & 3) << 2;          // 0,4,8,12
            float4 va = *(const float4*)(Ablk + (size_t)row * K + k0 + kq);
            As[kq + 0][row] = va.x; As[kq + 1][row] = va.y;
            As[kq + 2][row] = va.z; As[kq + 3][row] = va.w;
            float4 vb = *(const float4*)(Bblk + (size_t)row * K + k0 + kq);
            Bs[kq + 0][row] = vb.x; Bs[kq + 1][row] = vb.y;
            Bs[kq + 2][row] = vb.z; Bs[kq + 3][row] = vb.w;
        }
        __syncthreads();
#pragma unroll
        for (int k = 0; k < 16; k++) {
            float a[8], b[8];
            *(float4*)(a)     = *(const float4*)&As[k][ty * 8];
            *(float4*)(a + 4) = *(const float4*)&As[k][ty * 8 + 4];
            *(float4*)(b)     = *(const float4*)&Bs[k][tx * 8];
            *(float4*)(b + 4) = *(const float4*)&Bs[k][tx * 8 + 4];
#pragma unroll
            for (int i = 0; i < 8; i++)
#pragma unroll
                for (int j = 0; j < 8; j++)
                    acc[i][j] += a[i] * b[j];
        }
        __syncthreads();
    }

#pragma unroll
    for (int i = 0; i < 8; i++) {
        int m = by * 128 + ty * 8 + i;
        size_t off = (size_t)m * N + bx * 128 + tx * 8;
        float4 c0 = make_float4(acc[i][0], acc[i][1], acc[i][2], acc[i][3]);
        float4 c1 = make_float4(acc[i][4], acc[i][5], acc[i][6], acc[i][7]);
        if (EPI == 1) {
            float4 r0 = *(const float4*)(Rsd + off);
            float4 r1 = *(const float4*)(Rsd + off + 4);
            c0.x += r0.x; c0.y += r0.y; c0.z += r0.z; c0.w += r0.w;
            c1.x += r1.x; c1.y += r1.y; c1.z += r1.z; c1.w += r1.w;
        }
        *(float4*)(C + off)     = c0;
        *(float4*)(C + off + 4) = c1;
    }
}

// ---------------------------------------------------------------------------
// Attention scores: S[bh, q, k] = scale * (Q_row . K_row) + mask[q,k]
// 64x64 output tile per block, K-dim (=128) in two 64-chunks.
// Causal early-out: tiles with k0 > q0+63 are fully masked -> write NEG.
// ---------------------------------------------------------------------------
__global__ void __launch_bounds__(256) attn_scores(
    const float* __restrict__ qkv, const float* __restrict__ mask,
    float* __restrict__ scores)
{
    int bh = blockIdx.z;
    int b = bh >> 4, h = bh & 15;
    int q0 = blockIdx.y * 64;
    int k0 = blockIdx.x * 64;
    int tid = threadIdx.x;
    int ty = tid >> 4, tx = tid & 15;
    float* Sout = scores + ((size_t)bh * LL + q0) * LL + k0;

    if (k0 > q0 + 63) {
        float4 negv = make_float4(NEGV, NEGV, NEGV, NEGV);
#pragma unroll
        for (int i = 0; i < 4; i++)
            *(float4*)(Sout + (size_t)(ty * 4 + i) * LL + tx * 4) = negv;
        return;
    }

    __shared__ float Qt[64][64];   // [k][q-row]
    __shared__ float Kt[64][64];   // [k][k-row]
    float acc[4][4];
#pragma unroll
    for (int i = 0; i < 4; i++)
#pragma unroll
        for (int j = 0; j < 4; j++) acc[i][j] = 0.f;

    for (int hc = 0; hc < 2; hc++) {
#pragma unroll
        for (int t = 0; t < 4; t++) {
            int id = tid + t * 256;          // 0..1023
            int row = id >> 4;               // 0..63
            int cq = (id & 15) << 2;         // 0..60
            float4 vq = *(const float4*)(qkv +
                (size_t)(b * LL + q0 + row) * QKVD + h * HDD + hc * 64 + cq);
            Qt[cq + 0][row] = vq.x; Qt[cq + 1][row] = vq.y;
            Qt[cq + 2][row] = vq.z; Qt[cq + 3][row] = vq.w;
            float4 vk = *(const float4*)(qkv +
                (size_t)(b * LL + k0 + row) * QKVD + DD + h * HDD + hc * 64 + cq);
            Kt[cq + 0][row] = vk.x; Kt[cq + 1][row] = vk.y;
            Kt[cq + 2][row] = vk.z; Kt[cq + 3][row] = vk.w;
        }
        __syncthreads();
#pragma unroll
        for (int kk = 0; kk < 64; kk++) {
            float a[4], bb[4];
            *(float4*)a  = *(const float4*)&Qt[kk][ty * 4];
            *(float4*)bb = *(const float4*)&Kt[kk][tx * 4];
#pragma unroll
            for (int i = 0; i < 4; i++)
#pragma unroll
                for (int j = 0; j < 4; j++)
                    acc[i][j] += a[i] * bb[j];
        }
        __syncthreads();
    }

    const float scale = 0.088388347648318447f;  // 1/sqrt(128)
#pragma unroll
    for (int i = 0; i < 4; i++) {
        const float4 mrow = *(const float4*)(mask +
            (size_t)(q0 + ty * 4 + i) * LL + k0 + tx * 4);
        float4 c = make_float4(acc[i][0] * scale + mrow.x,
                               acc[i][1] * scale + mrow.y,
                               acc[i][2] * scale + mrow.z,
                               acc[i][3] * scale + mrow.w);
        *(float4*)(Sout + (size_t)(ty * 4 + i) * LL + tx * 4) = c;
    }
}

// ---------------------------------------------------------------------------
// Row softmax over L=2048, one block (256 thr) per row, in place.
// ---------------------------------------------------------------------------
__global__ void __launch_bounds__(256) softmax_rows(float* __restrict__ S)
{
    size_t row = blockIdx.x;
    float* p = S + row * (size_t)LL;
    int tid = threadIdx.x;
    float v[8];
    float m = -3.4e38f;
#pragma unroll
    for (int i = 0; i < 8; i++) {
        v[i] = p[tid + i * 256];
        m = fmaxf(m, v[i]);
    }
    __shared__ float red[256];
    red[tid] = m;
    __syncthreads();
    for (int o = 128; o > 0; o >>= 1) {
        if (tid < o) red[tid] = fmaxf(red[tid], red[tid + o]);
        __syncthreads();
    }
    float M = red[0];
    __syncthreads();
    float s = 0.f;
#pragma unroll
    for (int i = 0; i < 8; i++) {
        v[i] = expf(v[i] - M);
        s += v[i];
    }
    red[tid] = s;
    __syncthreads();
    for (int o = 128; o > 0; o >>= 1) {
        if (tid < o) red[tid] += red[tid + o];
        __syncthreads();
    }
    float inv = 1.0f / red[0];
#pragma unroll
    for (int i = 0; i < 8; i++) p[tid + i * 256] = v[i] * inv;
}

// ---------------------------------------------------------------------------
// PV: O[b, q, h, :] = sum_k P[bh, q, k] * V[b, k, h, :]
// Tile: 64 q-rows x 128 head dims per block; BK=32; causal k truncation.
// ---------------------------------------------------------------------------
__global__ void __launch_bounds__(256) attn_pv(
    const float* __restrict__ qkv, const float* __restrict__ P,
    float* __restrict__ O)
{
    int bh = blockIdx.z;
    int b = bh >> 4, h = bh & 15;
    int q0 = blockIdx.x * 64;
    int tid = threadIdx.x;
    int ty = tid >> 5;        // 0..7  -> 8 q-rows each
    int tx = tid & 31;        // 0..31 -> 4 dims each

    __shared__ float Pt[32][64];    // [k][q]
    __shared__ float Vs[32][128];   // [k][d]
    float acc[8][4];
#pragma unroll
    for (int i = 0; i < 8; i++)
#pragma unroll
        for (int j = 0; j < 4; j++) acc[i][j] = 0.f;

    const float* Prow = P + ((size_t)bh * LL + q0) * LL;
    int kend = q0 + 64;   // causal: P is exactly 0 beyond this

    for (int k0 = 0; k0 < kend; k0 += 32) {
#pragma unroll
        for (int t = 0; t < 2; t++) {
            int id = tid + t * 256;          // 0..511
            int row = id >> 3;               // 0..63 (q row)
            int kq = (id & 7) << 2;          // 0..28
            float4 vp = *(const float4*)(Prow + (size_t)row * LL + k0 + kq);
            Pt[kq + 0][row] = vp.x; Pt[kq + 1][row] = vp.y;
            Pt[kq + 2][row] = vp.z; Pt[kq + 3][row] = vp.w;
        }
#pragma unroll
        for (int t = 0; t < 4; t++) {
            int id = tid + t * 256;          // 0..1023
            int kr = id >> 5;                // 0..31
            int dq = (id & 31) << 2;         // 0..124
            float4 vv = *(const float4*)(qkv +
                (size_t)(b * LL + k0 + kr) * QKVD + 2 * DD + h * HDD + dq);
            *(float4*)&Vs[kr][dq] = vv;
        }
        __syncthreads();
#pragma unroll
        for (int k = 0; k < 32; k++) {
            float a[8];
            *(float4*)(a)     = *(const float4*)&Pt[k][ty * 8];
            *(float4*)(a + 4) = *(const float4*)&Pt[k][ty * 8 + 4];
            float4 bv = *(const float4*)&Vs[k][tx * 4];
#pragma unroll
            for (int i = 0; i < 8; i++) {
                acc[i][0] += a[i] * bv.x;
                acc[i][1] += a[i] * bv.y;
                acc[i][2] += a[i] * bv.z;
                acc[i][3] += a[i] * bv.w;
            }
        }
        __syncthreads();
    }

#pragma unroll
    for (int i = 0; i < 8; i++) {
        size_t off = (size_t)(b * LL + q0 + ty * 8 + i) * DD + h * HDD + tx * 4;
        *(float4*)(O + off) = make_float4(acc[i][0], acc[i][1], acc[i][2], acc[i][3]);
    }
}

// ---------------------------------------------------------------------------
// ff = silu(gate) * up, in place into gate. n multiple of 1024.
// ---------------------------------------------------------------------------
__global__ void __launch_bounds__(256) silu_mul(
    float* __restrict__ gate, const float* __restrict__ up)
{
    size_t i = ((size_t)blockIdx.x * 256 + threadIdx.x) * 4;
    float4 g = *(const float4*)(gate + i);
    float4 u = *(const float4*)(up + i);
    g.x = g.x / (1.f + expf(-g.x)) * u.x;
    g.y = g.y / (1.f + expf(-g.y)) * u.y;
    g.z = g.z / (1.f + expf(-g.z)) * u.z;
    g.w = g.w / (1.f + expf(-g.w)) * u.w;
    *(float4*)(gate + i) = g;
}

// ---------------------------------------------------------------------------
// Launch
// ---------------------------------------------------------------------------
extern "C" void kernel_launch(void* const* d_in, const int* in_sizes, int n_in,
                              void* d_out, int out_size)
{
    const float* x       = (const float*)d_in[0];
    const float* mask    = (const float*)d_in[1];
    const float* norm1_w = (const float*)d_in[2];
    const float* qkv_w   = (const float*)d_in[3];
    const float* out_w   = (const float*)d_in[4];
    const float* norm2_w = (const float*)d_in[5];
    const float* gate_w  = (const float*)d_in[6];
    const float* up_w    = (const float*)d_in[7];
    const float* down_w  = (const float*)d_in[8];
    float* out = (float*)d_out;

    float *h1, *qkvb, *scores, *o, *x2, *h2, *gate, *up;
    cudaGetSymbolAddress((void**)&h1,     g_h1);
    cudaGetSymbolAddress((void**)&qkvb,   g_qkv);
    cudaGetSymbolAddress((void**)&scores, g_scores);
    cudaGetSymbolAddress((void**)&o,      g_o);
    cudaGetSymbolAddress((void**)&x2,     g_x2);
    cudaGetSymbolAddress((void**)&h2,     g_h2);
    cudaGetSymbolAddress((void**)&gate,   g_gate);
    cudaGetSymbolAddress((void**)&up,     g_up);

    // 1. h1 = rmsnorm(x, norm1_w)
    rmsnorm_kernel<<<RR, 256>>>(x, norm1_w, h1);

    // 2. qkv = h1 @ qkv_w^T      [4096 x 6144]
    gemm_nt<0><<<dim3(QKVD / 128, RR / 128), 256>>>(h1, qkv_w, nullptr, qkvb,
                                                    RR, QKVD, DD);

    // 3. scores = scale * Q K^T + mask
    attn_scores<<<dim3(LL / 64, LL / 64, BB * HH), 256>>>(qkvb, mask, scores);

    // 4. softmax rows
    softmax_rows<<<BB * HH * LL, 256>>>(scores);

    // 5. O = P @ V  (into (b,l,h,d) layout)
    attn_pv<<<dim3(LL / 64, 1, BB * HH), 256>>>(qkvb, scores, o);

    // 6. x2 = x + O @ out_w^T
    gemm_nt<1><<<dim3(DD / 128, RR / 128), 256>>>(o, out_w, x, x2, RR, DD, DD);

    // 7. h2 = rmsnorm(x2, norm2_w)
    rmsnorm_kernel<<<RR, 256>>>(x2, norm2_w, h2);

    // 8. gate = h2 @ gate_w^T ; up = h2 @ up_w^T
    gemm_nt<0><<<dim3(FF_ / 128, RR / 128), 256>>>(h2, gate_w, nullptr, gate,
                                                   RR, FF_, DD);
    gemm_nt<0><<<dim3(FF_ / 128, RR / 128), 256>>>(h2, up_w, nullptr, up,
                                                   RR, FF_, DD);

    // 9. ff = silu(gate) * up  (in place into gate)
    silu_mul<<<(unsigned)(((size_t)RR * FF_) / 1024), 256>>>(gate, up);

    // 10. out = x2 + ff @ down_w^T
    gemm_nt<1><<<dim3(DD / 128, RR / 128), 256>>>(gate, down_w, x2, out,
                                                  RR, DD, FF_);
}

// round 4
// speedup vs baseline: 2.5401x; 2.5401x over previous
#include <cuda_runtime.h>
#include <math.h>
#include <stdint.h>
#include <stddef.h>

// Problem constants
#define BB   2
#define LL   2048
#define DD   2048
#define HH   16
#define HDD  128
#define FF_  8192
#define RR   4096          // B*L
#define QKVD 6144          // 3*D
#define NEGV (-1000000000.0f)

// ---------------------------------------------------------------------------
// Scratch (allocation-free: __device__ globals)
// ---------------------------------------------------------------------------
__device__ float g_h1[(size_t)RR * DD];
__device__ float g_qkv[(size_t)RR * QKVD];
__device__ float g_scores[(size_t)BB * HH * LL * LL];
__device__ float g_o[(size_t)RR * DD];
__device__ float g_x2[(size_t)RR * DD];
__device__ float g_h2[(size_t)RR * DD];
__device__ float g_gate[(size_t)RR * FF_];
__device__ float g_up[(size_t)RR * FF_];

// ---------------------------------------------------------------------------
// Helpers (all sm_80-level PTX: compiles at compute_103)
// ---------------------------------------------------------------------------
__device__ __forceinline__ uint32_t smem_u32(const void* p) {
    uint32_t a;
    asm("{ .reg .u64 t; cvta.to.shared.u64 t, %1; cvt.u32.u64 %0, t; }"
        : "=r"(a) : "l"(p));
    return a;
}
__device__ __forceinline__ uint32_t f2tf32(float x) {
    uint32_t r;
    asm("cvt.rna.tf32.f32 %0, %1;" : "=r"(r) : "f"(x));
    return r;
}
__device__ __forceinline__ void sts128(uint32_t a, uint32_t x, uint32_t y,
                                       uint32_t z, uint32_t w) {
    asm volatile("st.shared.v4.b32 [%0], {%1, %2, %3, %4};"
                 :: "r"(a), "r"(x), "r"(y), "r"(z), "r"(w) : "memory");
}
__device__ __forceinline__ void ldsm4(uint32_t* r, uint32_t addr) {
    asm volatile("ldmatrix.sync.aligned.m8n8.x4.shared.b16 {%0,%1,%2,%3}, [%4];"
                 : "=r"(r[0]), "=r"(r[1]), "=r"(r[2]), "=r"(r[3]) : "r"(addr));
}
__device__ __forceinline__ void mma_tf32(float* d, const uint32_t* a,
                                         uint32_t b0, uint32_t b1) {
    asm volatile(
        "mma.sync.aligned.m16n8k8.row.col.f32.tf32.tf32.f32 "
        "{%0,%1,%2,%3}, {%4,%5,%6,%7}, {%8,%9}, {%0,%1,%2,%3};"
        : "+f"(d[0]), "+f"(d[1]), "+f"(d[2]), "+f"(d[3])
        : "r"(a[0]), "r"(a[1]), "r"(a[2]), "r"(a[3]), "r"(b0), "r"(b1));
}
__device__ __forceinline__ uint32_t sw128(uint32_t off) {
    return off ^ ((off >> 3) & 0x70);
}

// ---------------------------------------------------------------------------
// tf32 mma.sync GEMM: C[M,N] = A[M,K] @ B[N,K]^T (+ residual if EPI)
// BM=128, BN=128, BK=32, 256 threads (8 warps: 4 in M x 2 in N).
// Warp tile 32(M) x 64(N); m16n8k8 fragments via swizzled ldmatrix.
// grid = (N/128, M/128). Requires K % 32 == 0.
// ---------------------------------------------------------------------------
#define STAGE_BYTES 32768u           // 16KB A + 16KB B
#define GEMM_SMEM   (2u * STAGE_BYTES)

template <int EPI>
__global__ void __launch_bounds__(256) gemm_mma(
    const float* __restrict__ A, const float* __restrict__ Bm,
    const float* __restrict__ Rsd, float* __restrict__ C,
    int N, int K)
{
    extern __shared__ char smem[];
    uint32_t sbase = smem_u32(smem);

    int tid = threadIdx.x;
    int lane = tid & 31, wid = tid >> 5;
    int wm = wid & 3, wn = wid >> 2;
    int bx = blockIdx.x, by = blockIdx.y;

    // ldmatrix lane decomposition: rows (lane&15), k-chunk select (lane>>4)
    int lrow = lane & 15;
    int lchunk = lane >> 4;

    // per-thread gmem load coords: chunk c (16B), base row r0
    int gc = tid & 7;        // 0..7  -> 16B chunk within 128B row
    int gr = tid >> 3;       // 0..31 -> row; passes add +32

    const float* Ag0 = A + (size_t)by * 128 * K;
    const float* Bg0 = Bm + (size_t)bx * 128 * K;

    // precomputed ldmatrix row offsets (logical byte offsets, pre-swizzle)
    uint32_t arow[2], brow[4];
#pragma unroll
    for (int mt = 0; mt < 2; mt++)
        arow[mt] = (uint32_t)((wm * 32 + mt * 16 + lrow) * 128);
#pragma unroll
    for (int nt2 = 0; nt2 < 4; nt2++)
        brow[nt2] = (uint32_t)((wn * 64 + nt2 * 16 + lrow) * 128);

    float acc[2][8][4];
#pragma unroll
    for (int mt = 0; mt < 2; mt++)
#pragma unroll
        for (int nt = 0; nt < 8; nt++)
#pragma unroll
            for (int i = 0; i < 4; i++) acc[mt][nt][i] = 0.f;

    int nkt = K / 32;
    float4 av[4], bv[4];

    // prologue: load tile 0 and store to stage 0
#pragma unroll
    for (int p = 0; p < 4; p++) {
        av[p] = *(const float4*)(Ag0 + (size_t)(gr + 32 * p) * K + gc * 4);
        bv[p] = *(const float4*)(Bg0 + (size_t)(gr + 32 * p) * K + gc * 4);
    }
#pragma unroll
    for (int p = 0; p < 4; p++) {
        uint32_t off = sw128((uint32_t)((gr + 32 * p) * 128 + gc * 16));
        sts128(sbase + off, f2tf32(av[p].x), f2tf32(av[p].y),
               f2tf32(av[p].z), f2tf32(av[p].w));
        sts128(sbase + 16384u + off, f2tf32(bv[p].x), f2tf32(bv[p].y),
               f2tf32(bv[p].z), f2tf32(bv[p].w));
    }
    __syncthreads();

    for (int kt = 0; kt < nkt; kt++) {
        uint32_t st = sbase + (uint32_t)(kt & 1) * STAGE_BYTES;

        // prefetch next tile into registers
        if (kt + 1 < nkt) {
            const float* An = Ag0 + (kt + 1) * 32;
            const float* Bn = Bg0 + (kt + 1) * 32;
#pragma unroll
            for (int p = 0; p < 4; p++) {
                av[p] = *(const float4*)(An + (size_t)(gr + 32 * p) * K + gc * 4);
                bv[p] = *(const float4*)(Bn + (size_t)(gr + 32 * p) * K + gc * 4);
            }
        }

        // compute from stage kt&1
        uint32_t sa = st, sbB = st + 16384u;
#pragma unroll
        for (int ks = 0; ks < 4; ks++) {
            uint32_t cb = (uint32_t)((ks * 2 + lchunk) * 16);
            uint32_t a[2][4], bq[4][4];
#pragma unroll
            for (int mt = 0; mt < 2; mt++)
                ldsm4(a[mt], sa + sw128(arow[mt] + cb));
#pragma unroll
            for (int nt2 = 0; nt2 < 4; nt2++)
                ldsm4(bq[nt2], sbB + sw128(brow[nt2] + cb));
#pragma unroll
            for (int mt = 0; mt < 2; mt++)
#pragma unroll
                for (int nt2 = 0; nt2 < 4; nt2++) {
                    mma_tf32(acc[mt][2 * nt2],     a[mt], bq[nt2][0], bq[nt2][2]);
                    mma_tf32(acc[mt][2 * nt2 + 1], a[mt], bq[nt2][1], bq[nt2][3]);
                }
        }
        __syncthreads();

        // store next tile into the other stage
        if (kt + 1 < nkt) {
            uint32_t sn = sbase + (uint32_t)((kt + 1) & 1) * STAGE_BYTES;
#pragma unroll
            for (int p = 0; p < 4; p++) {
                uint32_t off = sw128((uint32_t)((gr + 32 * p) * 128 + gc * 16));
                sts128(sn + off, f2tf32(av[p].x), f2tf32(av[p].y),
                       f2tf32(av[p].z), f2tf32(av[p].w));
                sts128(sn + 16384u + off, f2tf32(bv[p].x), f2tf32(bv[p].y),
                       f2tf32(bv[p].z), f2tf32(bv[p].w));
            }
            __syncthreads();
        }
    }

    // epilogue: c0,c1 at (row, 2c), (row, 2c+1); c2,c3 at (row+8, ...)
    int crow = by * 128 + wm * 32 + (lane >> 2);
    int ccol = bx * 128 + wn * 64 + (lane & 3) * 2;
#pragma unroll
    for (int mt = 0; mt < 2; mt++) {
#pragma unroll
        for (int nt = 0; nt < 8; nt++) {
            size_t r0 = (size_t)(crow + mt * 16) * N + (ccol + nt * 8);
            size_t r1 = r0 + 8 * (size_t)N;
            float2 c0 = make_float2(acc[mt][nt][0], acc[mt][nt][1]);
            float2 c1 = make_float2(acc[mt][nt][2], acc[mt][nt][3]);
            if (EPI == 1) {
                float2 x0 = *(const float2*)(Rsd + r0);
                float2 x1 = *(const float2*)(Rsd + r1);
                c0.x += x0.x; c0.y += x0.y;
                c1.x += x1.x; c1.y += x1.y;
            }
            *(float2*)(C + r0) = c0;
            *(float2*)(C + r1) = c1;
        }
    }
}

// ---------------------------------------------------------------------------
// RMSNorm
// ---------------------------------------------------------------------------
__global__ void __launch_bounds__(256) rmsnorm_kernel(
    const float* __restrict__ x, const float* __restrict__ w,
    float* __restrict__ out)
{
    int row = blockIdx.x;
    int tid = threadIdx.x;
    const float* xr = x + (size_t)row * DD;
    float v[8];
    float s = 0.f;
#pragma unroll
    for (int i = 0; i < 8; i++) {
        v[i] = xr[tid + i * 256];
        s += v[i] * v[i];
    }
    __shared__ float red[256];
    red[tid] = s;
    __syncthreads();
    for (int o = 128; o > 0; o >>= 1) {
        if (tid < o) red[tid] += red[tid + o];
        __syncthreads();
    }
    float rs = rsqrtf(red[0] / (float)DD + 1e-6f);
    float* orow = out + (size_t)row * DD;
#pragma unroll
    for (int i = 0; i < 8; i++) {
        int c = tid + i * 256;
        orow[c] = v[i] * rs * w[c];
    }
}

// ---------------------------------------------------------------------------
// Attention scores (fp32 SIMT, causal tile skip)
// ---------------------------------------------------------------------------
__global__ void __launch_bounds__(256) attn_scores(
    const float* __restrict__ qkv, const float* __restrict__ mask,
    float* __restrict__ scores)
{
    int bh = blockIdx.z;
    int b = bh >> 4, h = bh & 15;
    int q0 = blockIdx.y * 64;
    int k0 = blockIdx.x * 64;
    int tid = threadIdx.x;
    int ty = tid >> 4, tx = tid & 15;
    float* Sout = scores + ((size_t)bh * LL + q0) * LL + k0;

    if (k0 > q0 + 63) {
        float4 negv = make_float4(NEGV, NEGV, NEGV, NEGV);
#pragma unroll
        for (int i = 0; i < 4; i++)
            *(float4*)(Sout + (size_t)(ty * 4 + i) * LL + tx * 4) = negv;
        return;
    }

    __shared__ float Qt[64][64];
    __shared__ float Kt[64][64];
    float acc[4][4];
#pragma unroll
    for (int i = 0; i < 4; i++)
#pragma unroll
        for (int j = 0; j < 4; j++) acc[i][j] = 0.f;

    for (int hc = 0; hc < 2; hc++) {
#pragma unroll
        for (int t = 0; t < 4; t++) {
            int id = tid + t * 256;
            int row = id >> 4;
            int cq = (id & 15) << 2;
            float4 vq = *(const float4*)(qkv +
                (size_t)(b * LL + q0 + row) * QKVD + h * HDD + hc * 64 + cq);
            Qt[cq + 0][row] = vq.x; Qt[cq + 1][row] = vq.y;
            Qt[cq + 2][row] = vq.z; Qt[cq + 3][row] = vq.w;
            float4 vk = *(const float4*)(qkv +
                (size_t)(b * LL + k0 + row) * QKVD + DD + h * HDD + hc * 64 + cq);
            Kt[cq + 0][row] = vk.x; Kt[cq + 1][row] = vk.y;
            Kt[cq + 2][row] = vk.z; Kt[cq + 3][row] = vk.w;
        }
        __syncthreads();
#pragma unroll
        for (int kk = 0; kk < 64; kk++) {
            float a[4], bb[4];
            *(float4*)a  = *(const float4*)&Qt[kk][ty * 4];
            *(float4*)bb = *(const float4*)&Kt[kk][tx * 4];
#pragma unroll
            for (int i = 0; i < 4; i++)
#pragma unroll
                for (int j = 0; j < 4; j++)
                    acc[i][j] += a[i] * bb[j];
        }
        __syncthreads();
    }

    const float scale = 0.088388347648318447f;
#pragma unroll
    for (int i = 0; i < 4; i++) {
        const float4 mrow = *(const float4*)(mask +
            (size_t)(q0 + ty * 4 + i) * LL + k0 + tx * 4);
        float4 c = make_float4(acc[i][0] * scale + mrow.x,
                               acc[i][1] * scale + mrow.y,
                               acc[i][2] * scale + mrow.z,
                               acc[i][3] * scale + mrow.w);
        *(float4*)(Sout + (size_t)(ty * 4 + i) * LL + tx * 4) = c;
    }
}

// ---------------------------------------------------------------------------
// Row softmax (in place)
// ---------------------------------------------------------------------------
__global__ void __launch_bounds__(256) softmax_rows(float* __restrict__ S)
{
    size_t row = blockIdx.x;
    float* p = S + row * (size_t)LL;
    int tid = threadIdx.x;
    float v[8];
    float m = -3.4e38f;
#pragma unroll
    for (int i = 0; i < 8; i++) {
        v[i] = p[tid + i * 256];
        m = fmaxf(m, v[i]);
    }
    __shared__ float red[256];
    red[tid] = m;
    __syncthreads();
    for (int o = 128; o > 0; o >>= 1) {
        if (tid < o) red[tid] = fmaxf(red[tid], red[tid + o]);
        __syncthreads();
    }
    float M = red[0];
    __syncthreads();
    float s = 0.f;
#pragma unroll
    for (int i = 0; i < 8; i++) {
        v[i] = expf(v[i] - M);
        s += v[i];
    }
    red[tid] = s;
    __syncthreads();
    for (int o = 128; o > 0; o >>= 1) {
        if (tid < o) red[tid] += red[tid + o];
        __syncthreads();
    }
    float inv = 1.0f / red[0];
#pragma unroll
    for (int i = 0; i < 8; i++) p[tid + i * 256] = v[i] * inv;
}

// ---------------------------------------------------------------------------
// PV (fp32 SIMT, causal truncation)
// ---------------------------------------------------------------------------
__global__ void __launch_bounds__(256) attn_pv(
    const float* __restrict__ qkv, const float* __restrict__ P,
    float* __restrict__ O)
{
    int bh = blockIdx.z;
    int b = bh >> 4, h = bh & 15;
    int q0 = blockIdx.x * 64;
    int tid = threadIdx.x;
    int ty = tid >> 5;
    int tx = tid & 31;

    __shared__ float Pt[32][64];
    __shared__ float Vs[32][128];
    float acc[8][4];
#pragma unroll
    for (int i = 0; i < 8; i++)
#pragma unroll
        for (int j = 0; j < 4; j++) acc[i][j] = 0.f;

    const float* Prow = P + ((size_t)bh * LL + q0) * LL;
    int kend = q0 + 64;

    for (int k0 = 0; k0 < kend; k0 += 32) {
#pragma unroll
        for (int t = 0; t < 2; t++) {
            int id = tid + t * 256;
            int row = id >> 3;
            int kq = (id & 7) << 2;
            float4 vp = *(const float4*)(Prow + (size_t)row * LL + k0 + kq);
            Pt[kq + 0][row] = vp.x; Pt[kq + 1][row] = vp.y;
            Pt[kq + 2][row] = vp.z; Pt[kq + 3][row] = vp.w;
        }
#pragma unroll
        for (int t = 0; t < 4; t++) {
            int id = tid + t * 256;
            int kr = id >> 5;
            int dq = (id & 31) << 2;
            float4 vv = *(const float4*)(qkv +
                (size_t)(b * LL + k0 + kr) * QKVD + 2 * DD + h * HDD + dq);
            *(float4*)&Vs[kr][dq] = vv;
        }
        __syncthreads();
#pragma unroll
        for (int k = 0; k < 32; k++) {
            float a[8];
            *(float4*)(a)     = *(const float4*)&Pt[k][ty * 8];
            *(float4*)(a + 4) = *(const float4*)&Pt[k][ty * 8 + 4];
            float4 bv = *(const float4*)&Vs[k][tx * 4];
#pragma unroll
            for (int i = 0; i < 8; i++) {
                acc[i][0] += a[i] * bv.x;
                acc[i][1] += a[i] * bv.y;
                acc[i][2] += a[i] * bv.z;
                acc[i][3] += a[i] * bv.w;
            }
        }
        __syncthreads();
    }

#pragma unroll
    for (int i = 0; i < 8; i++) {
        size_t off = (size_t)(b * LL + q0 + ty * 8 + i) * DD + h * HDD + tx * 4;
        *(float4*)(O + off) = make_float4(acc[i][0], acc[i][1], acc[i][2], acc[i][3]);
    }
}

// ---------------------------------------------------------------------------
// silu(gate) * up in place
// ---------------------------------------------------------------------------
__global__ void __launch_bounds__(256) silu_mul(
    float* __restrict__ gate, const float* __restrict__ up)
{
    size_t i = ((size_t)blockIdx.x * 256 + threadIdx.x) * 4;
    float4 g = *(const float4*)(gate + i);
    float4 u = *(const float4*)(up + i);
    g.x = g.x / (1.f + expf(-g.x)) * u.x;
    g.y = g.y / (1.f + expf(-g.y)) * u.y;
    g.z = g.z / (1.f + expf(-g.z)) * u.z;
    g.w = g.w / (1.f + expf(-g.w)) * u.w;
    *(float4*)(gate + i) = g;
}

// ---------------------------------------------------------------------------
// Launch
// ---------------------------------------------------------------------------
extern "C" void kernel_launch(void* const* d_in, const int* in_sizes, int n_in,
                              void* d_out, int out_size)
{
    const float* x       = (const float*)d_in[0];
    const float* mask    = (const float*)d_in[1];
    const float* norm1_w = (const float*)d_in[2];
    const float* qkv_w   = (const float*)d_in[3];
    const float* out_w   = (const float*)d_in[4];
    const float* norm2_w = (const float*)d_in[5];
    const float* gate_w  = (const float*)d_in[6];
    const float* up_w    = (const float*)d_in[7];
    const float* down_w  = (const float*)d_in[8];
    float* out = (float*)d_out;

    float *h1, *qkvb, *scores, *o, *x2, *h2, *gate, *up;
    cudaGetSymbolAddress((void**)&h1,     g_h1);
    cudaGetSymbolAddress((void**)&qkvb,   g_qkv);
    cudaGetSymbolAddress((void**)&scores, g_scores);
    cudaGetSymbolAddress((void**)&o,      g_o);
    cudaGetSymbolAddress((void**)&x2,     g_x2);
    cudaGetSymbolAddress((void**)&h2,     g_h2);
    cudaGetSymbolAddress((void**)&gate,   g_gate);
    cudaGetSymbolAddress((void**)&up,     g_up);

    cudaFuncSetAttribute(gemm_mma<0>, cudaFuncAttributeMaxDynamicSharedMemorySize, GEMM_SMEM);
    cudaFuncSetAttribute(gemm_mma<1>, cudaFuncAttributeMaxDynamicSharedMemorySize, GEMM_SMEM);

    // 1. h1 = rmsnorm(x)
    rmsnorm_kernel<<<RR, 256>>>(x, norm1_w, h1);

    // 2. qkv = h1 @ qkv_w^T
    gemm_mma<0><<<dim3(QKVD / 128, RR / 128), 256, GEMM_SMEM>>>(
        h1, qkv_w, nullptr, qkvb, QKVD, DD);

    // 3-5. attention (fp32)
    attn_scores<<<dim3(LL / 64, LL / 64, BB * HH), 256>>>(qkvb, mask, scores);
    softmax_rows<<<BB * HH * LL, 256>>>(scores);
    attn_pv<<<dim3(LL / 64, 1, BB * HH), 256>>>(qkvb, scores, o);

    // 6. x2 = x + O @ out_w^T
    gemm_mma<1><<<dim3(DD / 128, RR / 128), 256, GEMM_SMEM>>>(
        o, out_w, x, x2, DD, DD);

    // 7. h2 = rmsnorm(x2)
    rmsnorm_kernel<<<RR, 256>>>(x2, norm2_w, h2);

    // 8. gate / up projections
    gemm_mma<0><<<dim3(FF_ / 128, RR / 128), 256, GEMM_SMEM>>>(
        h2, gate_w, nullptr, gate, FF_, DD);
    gemm_mma<0><<<dim3(FF_ / 128, RR / 128), 256, GEMM_SMEM>>>(
        h2, up_w, nullptr, up, FF_, DD);

    // 9. silu(gate)*up
    silu_mul<<<(unsigned)(((size_t)RR * FF_) / 1024), 256>>>(gate, up);

    // 10. out = x2 + ff @ down_w^T
    gemm_mma<1><<<dim3(DD / 128, RR / 128), 256, GEMM_SMEM>>>(
        gate, down_w, x2, out, DD, FF_);
}

// round 5
// speedup vs baseline: 7.0691x; 2.7830x over previous
#include <cuda_runtime.h>
#include <cuda_fp16.h>
#include <math.h>
#include <stdint.h>
#include <stddef.h>

// Problem constants
#define BB   2
#define LL   2048
#define DD   2048
#define HH   16
#define HDD  128
#define FF_  8192
#define RR   4096          // B*L
#define QKVD 6144          // 3*D

// ---------------------------------------------------------------------------
// Scratch (allocation-free: __device__ globals)
// ---------------------------------------------------------------------------
__device__ __half g_wqkv[(size_t)QKVD * DD];
__device__ __half g_wout[(size_t)DD * DD];
__device__ __half g_wgate[(size_t)FF_ * DD];
__device__ __half g_wup[(size_t)FF_ * DD];
__device__ __half g_wdown[(size_t)DD * FF_];

__device__ __half g_h1[(size_t)RR * DD];
__device__ __half g_qkv[(size_t)RR * QKVD];
__device__ float  g_scores[(size_t)BB * HH * LL * LL];
__device__ __half g_p[(size_t)BB * HH * LL * LL];
__device__ __half g_o[(size_t)RR * DD];
__device__ float  g_x2[(size_t)RR * DD];
__device__ __half g_h2[(size_t)RR * DD];
__device__ float  g_gate[(size_t)RR * FF_];
__device__ float  g_up[(size_t)RR * FF_];
__device__ __half g_ff[(size_t)RR * FF_];

// ---------------------------------------------------------------------------
// PTX helpers (sm_80-level: compiles at compute_103)
// ---------------------------------------------------------------------------
__device__ __forceinline__ uint32_t smem_u32(const void* p) {
    uint32_t a;
    asm("{ .reg .u64 t; cvta.to.shared.u64 t, %1; cvt.u32.u64 %0, t; }"
        : "=r"(a) : "l"(p));
    return a;
}
__device__ __forceinline__ void cp16(uint32_t s, const void* g) {
    asm volatile("cp.async.cg.shared.global [%0], [%1], 16;"
                 :: "r"(s), "l"(g) : "memory");
}
__device__ __forceinline__ void cp_commit() {
    asm volatile("cp.async.commit_group;" ::: "memory");
}
template <int N>
__device__ __forceinline__ void cp_wait() {
    asm volatile("cp.async.wait_group %0;" :: "n"(N) : "memory");
}
__device__ __forceinline__ void ldsm4(uint32_t* r, uint32_t addr) {
    asm volatile("ldmatrix.sync.aligned.m8n8.x4.shared.b16 {%0,%1,%2,%3}, [%4];"
                 : "=r"(r[0]), "=r"(r[1]), "=r"(r[2]), "=r"(r[3]) : "r"(addr));
}
__device__ __forceinline__ void ldsm4t(uint32_t* r, uint32_t addr) {
    asm volatile("ldmatrix.sync.aligned.m8n8.x4.trans.shared.b16 {%0,%1,%2,%3}, [%4];"
                 : "=r"(r[0]), "=r"(r[1]), "=r"(r[2]), "=r"(r[3]) : "r"(addr));
}
__device__ __forceinline__ void mma_f16(float* d, const uint32_t* a,
                                        uint32_t b0, uint32_t b1) {
    asm volatile(
        "mma.sync.aligned.m16n8k16.row.col.f32.f16.f16.f32 "
        "{%0,%1,%2,%3}, {%4,%5,%6,%7}, {%8,%9}, {%0,%1,%2,%3};"
        : "+f"(d[0]), "+f"(d[1]), "+f"(d[2]), "+f"(d[3])
        : "r"(a[0]), "r"(a[1]), "r"(a[2]), "r"(a[3]), "r"(b0), "r"(b1));
}
__device__ __forceinline__ uint32_t sw128(uint32_t off) {
    return off ^ ((off >> 3) & 0x70);
}

// ---------------------------------------------------------------------------
// fp32 -> fp16 convert (n multiple of 1024)
// ---------------------------------------------------------------------------
__global__ void __launch_bounds__(256) f2h_kernel(
    const float* __restrict__ s, __half* __restrict__ d)
{
    size_t i = ((size_t)blockIdx.x * 256 + threadIdx.x) * 4;
    float4 v = *(const float4*)(s + i);
    *(__half2*)(d + i)     = __floats2half2_rn(v.x, v.y);
    *(__half2*)(d + i + 2) = __floats2half2_rn(v.z, v.w);
}

// ---------------------------------------------------------------------------
// RMSNorm -> fp16 output
// ---------------------------------------------------------------------------
__global__ void __launch_bounds__(256) rmsnorm_h(
    const float* __restrict__ x, const float* __restrict__ w,
    __half* __restrict__ out)
{
    int row = blockIdx.x;
    int tid = threadIdx.x;
    const float* xr = x + (size_t)row * DD;
    float v[8];
    float s = 0.f;
#pragma unroll
    for (int i = 0; i < 8; i++) {
        v[i] = xr[tid + i * 256];
        s += v[i] * v[i];
    }
    __shared__ float red[256];
    red[tid] = s;
    __syncthreads();
    for (int o = 128; o > 0; o >>= 1) {
        if (tid < o) red[tid] += red[tid + o];
        __syncthreads();
    }
    float rs = rsqrtf(red[0] / (float)DD + 1e-6f);
    __half* orow = out + (size_t)row * DD;
#pragma unroll
    for (int i = 0; i < 8; i++) {
        int c = tid + i * 256;
        orow[c] = __float2half_rn(v[i] * rs * w[c]);
    }
}

// ---------------------------------------------------------------------------
// fp16 mma GEMM: C[M,N] = A[M,K] @ B[N,K]^T (+ fp32 residual), fp16 in smem.
// BM=BN=128, BK=64, 256 thr (8 warps: 4M x 2N), warp tile 32x64.
// cp.async double buffer (2 x 32KB). grid = (N/128, M/128). K%64==0.
// OUTH: 1 -> fp16 C, 0 -> fp32 C.
// ---------------------------------------------------------------------------
#define GEMM_SMEM 65536

template <int OUTH, int EPI>
__global__ void __launch_bounds__(256) gemm_h(
    const __half* __restrict__ A, const __half* __restrict__ B,
    const float* __restrict__ Rsd, void* __restrict__ Cv, int N, int K)
{
    extern __shared__ char smem[];
    uint32_t sbase = smem_u32(smem);
    int tid = threadIdx.x, lane = tid & 31, wid = tid >> 5;
    int wm = wid & 3, wn = wid >> 2;
    int bx = blockIdx.x, by = blockIdx.y;
    int lrow = lane & 15, lchunk = lane >> 4;
    int gc = tid & 7, gr = tid >> 3;

    const __half* Ag = A + (size_t)by * 128 * K + gc * 8;
    const __half* Bg = B + (size_t)bx * 128 * K + gc * 8;

    uint32_t stoff[4];
#pragma unroll
    for (int p = 0; p < 4; p++)
        stoff[p] = sw128((uint32_t)((gr + 32 * p) * 128 + gc * 16));

    uint32_t arow[2], brow[4];
#pragma unroll
    for (int mt = 0; mt < 2; mt++)
        arow[mt] = (uint32_t)((wm * 32 + mt * 16 + lrow) * 128);
#pragma unroll
    for (int nt2 = 0; nt2 < 4; nt2++)
        brow[nt2] = (uint32_t)((wn * 64 + nt2 * 16 + lrow) * 128);

    float acc[2][8][4];
#pragma unroll
    for (int mt = 0; mt < 2; mt++)
#pragma unroll
        for (int nt = 0; nt < 8; nt++)
#pragma unroll
            for (int i = 0; i < 4; i++) acc[mt][nt][i] = 0.f;

    int nkt = K / 64;

    // prologue: issue tile 0 into stage 0
#pragma unroll
    for (int p = 0; p < 4; p++) {
        cp16(sbase + stoff[p], Ag + (size_t)(gr + 32 * p) * K);
        cp16(sbase + 16384u + stoff[p], Bg + (size_t)(gr + 32 * p) * K);
    }
    cp_commit();

    for (int kt = 0; kt < nkt; kt++) {
        uint32_t st = sbase + (uint32_t)(kt & 1) * 32768u;
        if (kt + 1 < nkt) {
            uint32_t sn = sbase + (uint32_t)((kt + 1) & 1) * 32768u;
            const __half* An = Ag + (kt + 1) * 64;
            const __half* Bn = Bg + (kt + 1) * 64;
#pragma unroll
            for (int p = 0; p < 4; p++) {
                cp16(sn + stoff[p], An + (size_t)(gr + 32 * p) * K);
                cp16(sn + 16384u + stoff[p], Bn + (size_t)(gr + 32 * p) * K);
            }
            cp_commit();
            cp_wait<1>();
        } else {
            cp_wait<0>();
        }
        __syncthreads();

#pragma unroll
        for (int ks = 0; ks < 4; ks++) {
            uint32_t cb = (uint32_t)(ks * 32 + lchunk * 16);
            uint32_t a[2][4], bq[4][4];
#pragma unroll
            for (int mt = 0; mt < 2; mt++)
                ldsm4(a[mt], st + sw128(arow[mt] + cb));
#pragma unroll
            for (int nt2 = 0; nt2 < 4; nt2++)
                ldsm4(bq[nt2], st + 16384u + sw128(brow[nt2] + cb));
#pragma unroll
            for (int mt = 0; mt < 2; mt++)
#pragma unroll
                for (int nt2 = 0; nt2 < 4; nt2++) {
                    mma_f16(acc[mt][2 * nt2],     a[mt], bq[nt2][0], bq[nt2][2]);
                    mma_f16(acc[mt][2 * nt2 + 1], a[mt], bq[nt2][1], bq[nt2][3]);
                }
        }
        __syncthreads();
    }

    int crow = by * 128 + wm * 32 + (lane >> 2);
    int ccol = bx * 128 + wn * 64 + (lane & 3) * 2;
#pragma unroll
    for (int mt = 0; mt < 2; mt++) {
#pragma unroll
        for (int nt = 0; nt < 8; nt++) {
            size_t r0 = (size_t)(crow + mt * 16) * N + (ccol + nt * 8);
            size_t r1 = r0 + 8 * (size_t)N;
            float c0 = acc[mt][nt][0], c1 = acc[mt][nt][1];
            float c2 = acc[mt][nt][2], c3 = acc[mt][nt][3];
            if (EPI == 1) {
                float2 x0 = *(const float2*)(Rsd + r0);
                float2 x1 = *(const float2*)(Rsd + r1);
                c0 += x0.x; c1 += x0.y; c2 += x1.x; c3 += x1.y;
            }
            if (OUTH == 1) {
                __half* C = (__half*)Cv;
                *(__half2*)(C + r0) = __floats2half2_rn(c0, c1);
                *(__half2*)(C + r1) = __floats2half2_rn(c2, c3);
            } else {
                float* C = (float*)Cv;
                *(float2*)(C + r0) = make_float2(c0, c1);
                *(float2*)(C + r1) = make_float2(c2, c3);
            }
        }
    }
}

// ---------------------------------------------------------------------------
// Attention scores (fp16 mma): S = scale*Q K^T + mask, 128x128 tiles,
// strictly-upper tiles skipped (softmax never reads them).
// ---------------------------------------------------------------------------
#define SC_SMEM 32768

__global__ void __launch_bounds__(256) attn_scores_h(
    const __half* __restrict__ qkv, const float* __restrict__ mask,
    float* __restrict__ scores)
{
    int bh = blockIdx.z;
    int q0 = blockIdx.y * 128;
    int k0 = blockIdx.x * 128;
    if (k0 > q0) return;
    int b = bh >> 4, h = bh & 15;

    extern __shared__ char smem[];
    uint32_t sbase = smem_u32(smem);
    int tid = threadIdx.x, lane = tid & 31, wid = tid >> 5;
    int wm = wid & 3, wn = wid >> 2;
    int lrow = lane & 15, lchunk = lane >> 4;
    int gc = tid & 7, gr = tid >> 3;

    uint32_t stoff[4];
#pragma unroll
    for (int p = 0; p < 4; p++)
        stoff[p] = sw128((uint32_t)((gr + 32 * p) * 128 + gc * 16));
    uint32_t arow[2], brow[4];
#pragma unroll
    for (int mt = 0; mt < 2; mt++)
        arow[mt] = (uint32_t)((wm * 32 + mt * 16 + lrow) * 128);
#pragma unroll
    for (int nt2 = 0; nt2 < 4; nt2++)
        brow[nt2] = (uint32_t)((wn * 64 + nt2 * 16 + lrow) * 128);

    float acc[2][8][4];
#pragma unroll
    for (int mt = 0; mt < 2; mt++)
#pragma unroll
        for (int nt = 0; nt < 8; nt++)
#pragma unroll
            for (int i = 0; i < 4; i++) acc[mt][nt][i] = 0.f;

    for (int hc = 0; hc < 2; hc++) {
#pragma unroll
        for (int p = 0; p < 4; p++) {
            cp16(sbase + stoff[p], qkv +
                 (size_t)(b * LL + q0 + gr + 32 * p) * QKVD + h * HDD + hc * 64 + gc * 8);
            cp16(sbase + 16384u + stoff[p], qkv +
                 (size_t)(b * LL + k0 + gr + 32 * p) * QKVD + DD + h * HDD + hc * 64 + gc * 8);
        }
        cp_commit();
        cp_wait<0>();
        __syncthreads();
#pragma unroll
        for (int ks = 0; ks < 4; ks++) {
            uint32_t cb = (uint32_t)(ks * 32 + lchunk * 16);
            uint32_t a[2][4], bq[4][4];
#pragma unroll
            for (int mt = 0; mt < 2; mt++)
                ldsm4(a[mt], sbase + sw128(arow[mt] + cb));
#pragma unroll
            for (int nt2 = 0; nt2 < 4; nt2++)
                ldsm4(bq[nt2], sbase + 16384u + sw128(brow[nt2] + cb));
#pragma unroll
            for (int mt = 0; mt < 2; mt++)
#pragma unroll
                for (int nt2 = 0; nt2 < 4; nt2++) {
                    mma_f16(acc[mt][2 * nt2],     a[mt], bq[nt2][0], bq[nt2][2]);
                    mma_f16(acc[mt][2 * nt2 + 1], a[mt], bq[nt2][1], bq[nt2][3]);
                }
        }
        __syncthreads();
    }

    const float scale = 0.088388347648318447f;  // 1/sqrt(128)
    int crow = q0 + wm * 32 + (lane >> 2);
    int ccol = k0 + wn * 64 + (lane & 3) * 2;
    float* Sb = scores + (size_t)bh * LL * LL;
#pragma unroll
    for (int mt = 0; mt < 2; mt++) {
#pragma unroll
        for (int nt = 0; nt < 8; nt++) {
            int q = crow + mt * 16;
            int k = ccol + nt * 8;
            float2 m0 = *(const float2*)(mask + (size_t)q * LL + k);
            float2 m1 = *(const float2*)(mask + (size_t)(q + 8) * LL + k);
            *(float2*)(Sb + (size_t)q * LL + k) =
                make_float2(acc[mt][nt][0] * scale + m0.x,
                            acc[mt][nt][1] * scale + m0.y);
            *(float2*)(Sb + (size_t)(q + 8) * LL + k) =
                make_float2(acc[mt][nt][2] * scale + m1.x,
                            acc[mt][nt][3] * scale + m1.y);
        }
    }
}

// ---------------------------------------------------------------------------
// Causal softmax: row q reads k in [0, q], writes fp16 P, zero-fills to
// the 128-tile boundary (everything past that is never read by PV).
// ---------------------------------------------------------------------------
__global__ void __launch_bounds__(256) softmax_causal(
    const float* __restrict__ S, __half* __restrict__ P)
{
    int row = blockIdx.x;
    int q = row & (LL - 1);
    int len = q + 1;
    int kend = ((q >> 7) + 1) << 7;
    const float* p = S + (size_t)row * LL;
    __half* o = P + (size_t)row * LL;
    int tid = threadIdx.x;
    float v[8];
    int nv = 0;
    float m = -3.4e38f;
    for (int i = tid; i < len; i += 256) {
        float x = p[i];
        v[nv++] = x;
        m = fmaxf(m, x);
    }
    __shared__ float red[256];
    red[tid] = m;
    __syncthreads();
    for (int o2 = 128; o2 > 0; o2 >>= 1) {
        if (tid < o2) red[tid] = fmaxf(red[tid], red[tid + o2]);
        __syncthreads();
    }
    float M = red[0];
    __syncthreads();
    float s = 0.f;
    for (int j = 0; j < nv; j++) {
        v[j] = expf(v[j] - M);
        s += v[j];
    }
    red[tid] = s;
    __syncthreads();
    for (int o2 = 128; o2 > 0; o2 >>= 1) {
        if (tid < o2) red[tid] += red[tid + o2];
        __syncthreads();
    }
    float inv = 1.0f / red[0];
    int j = 0;
    for (int i = tid; i < kend; i += 256) {
        float val = (i < len) ? v[j++] * inv : 0.f;
        o[i] = __float2half_rn(val);
    }
}

// ---------------------------------------------------------------------------
// PV (fp16 mma): O[b,q,h,:] = P[bh,q,:kend] @ V[:kend,:], kend = q0+128.
// 128 q-rows x 128 d per block, BK=64, cp.async double buffer.
// V needs transpose -> ldmatrix.trans; V smem stored as 2 d-halves of 128B rows.
// ---------------------------------------------------------------------------
#define PV_SMEM 65536

__global__ void __launch_bounds__(256) attn_pv_h(
    const __half* __restrict__ qkv, const __half* __restrict__ P,
    __half* __restrict__ O)
{
    int bh = blockIdx.y;
    int b = bh >> 4, h = bh & 15;
    int q0 = blockIdx.x * 128;

    extern __shared__ char smem[];
    uint32_t sbase = smem_u32(smem);
    int tid = threadIdx.x, lane = tid & 31, wid = tid >> 5;
    int wm = wid & 3, wn = wid >> 2;
    int lrow = lane & 15, lchunk = lane >> 4;
    int gc = tid & 7, gr = tid >> 3;

    uint32_t stoffP[4];
#pragma unroll
    for (int p = 0; p < 4; p++)
        stoffP[p] = sw128((uint32_t)((gr + 32 * p) * 128 + gc * 16));
    uint32_t arow[2];
#pragma unroll
    for (int mt = 0; mt < 2; mt++)
        arow[mt] = (uint32_t)((wm * 32 + mt * 16 + lrow) * 128);

    const __half* Pg = P + ((size_t)bh * LL + q0) * LL + gc * 8;

    float acc[2][8][4];
#pragma unroll
    for (int mt = 0; mt < 2; mt++)
#pragma unroll
        for (int nt = 0; nt < 8; nt++)
#pragma unroll
            for (int i = 0; i < 4; i++) acc[mt][nt][i] = 0.f;

    int nkt = (q0 + 128) / 64;

    // V loads: thread handles chunk idx = tid + p*256; kr = idx>>4, c = idx&15
    // prologue: stage 0 (k0 = 0)
    {
#pragma unroll
        for (int p = 0; p < 4; p++)
            cp16(sbase + stoffP[p], Pg + (size_t)(gr + 32 * p) * LL);
#pragma unroll
        for (int p = 0; p < 4; p++) {
            int idx = tid + p * 256;
            int kr = idx >> 4, c = idx & 15;
            cp16(sbase + 16384u + (uint32_t)((c >> 3) * 8192) +
                     sw128((uint32_t)(kr * 128 + (c & 7) * 16)),
                 qkv + (size_t)(b * LL + kr) * QKVD + 2 * DD + h * HDD + c * 8);
        }
        cp_commit();
    }

    for (int kt = 0; kt < nkt; kt++) {
        uint32_t st = sbase + (uint32_t)(kt & 1) * 32768u;
        if (kt + 1 < nkt) {
            uint32_t sn = sbase + (uint32_t)((kt + 1) & 1) * 32768u;
            int k0n = (kt + 1) * 64;
#pragma unroll
            for (int p = 0; p < 4; p++)
                cp16(sn + stoffP[p], Pg + (size_t)(gr + 32 * p) * LL + k0n);
#pragma unroll
            for (int p = 0; p < 4; p++) {
                int idx = tid + p * 256;
                int kr = idx >> 4, c = idx & 15;
                cp16(sn + 16384u + (uint32_t)((c >> 3) * 8192) +
                         sw128((uint32_t)(kr * 128 + (c & 7) * 16)),
                     qkv + (size_t)(b * LL + k0n + kr) * QKVD + 2 * DD + h * HDD + c * 8);
            }
            cp_commit();
            cp_wait<1>();
        } else {
            cp_wait<0>();
        }
        __syncthreads();

        uint32_t vb = st + 16384u + (uint32_t)(wn * 8192);
#pragma unroll
        for (int ks = 0; ks < 4; ks++) {
            uint32_t a[2][4], bq[4][4];
#pragma unroll
            for (int mt = 0; mt < 2; mt++)
                ldsm4(a[mt], st + sw128(arow[mt] + (uint32_t)(ks * 32 + lchunk * 16)));
#pragma unroll
            for (int nt2 = 0; nt2 < 4; nt2++)
                ldsm4t(bq[nt2], vb + sw128((uint32_t)((ks * 16 + lrow) * 128 +
                                                      nt2 * 32 + lchunk * 16)));
#pragma unroll
            for (int mt = 0; mt < 2; mt++)
#pragma unroll
                for (int nt2 = 0; nt2 < 4; nt2++) {
                    mma_f16(acc[mt][2 * nt2],     a[mt], bq[nt2][0], bq[nt2][1]);
                    mma_f16(acc[mt][2 * nt2 + 1], a[mt], bq[nt2][2], bq[nt2][3]);
                }
        }
        __syncthreads();
    }

    int crow = q0 + wm * 32 + (lane >> 2);
    int ccol = wn * 64 + (lane & 3) * 2;
#pragma unroll
    for (int mt = 0; mt < 2; mt++) {
#pragma unroll
        for (int nt = 0; nt < 8; nt++) {
            size_t r0 = (size_t)(b * LL + crow + mt * 16) * DD + h * HDD + ccol + nt * 8;
            size_t r1 = r0 + 8 * (size_t)DD;
            *(__half2*)(O + r0) = __floats2half2_rn(acc[mt][nt][0], acc[mt][nt][1]);
            *(__half2*)(O + r1) = __floats2half2_rn(acc[mt][nt][2], acc[mt][nt][3]);
        }
    }
}

// ---------------------------------------------------------------------------
// ff = silu(gate) * up -> fp16
// ---------------------------------------------------------------------------
__global__ void __launch_bounds__(256) silu_mul_h(
    const float* __restrict__ gate, const float* __restrict__ up,
    __half* __restrict__ ff)
{
    size_t i = ((size_t)blockIdx.x * 256 + threadIdx.x) * 4;
    float4 g = *(const float4*)(gate + i);
    float4 u = *(const float4*)(up + i);
    g.x = g.x / (1.f + expf(-g.x)) * u.x;
    g.y = g.y / (1.f + expf(-g.y)) * u.y;
    g.z = g.z / (1.f + expf(-g.z)) * u.z;
    g.w = g.w / (1.f + expf(-g.w)) * u.w;
    *(__half2*)(ff + i)     = __floats2half2_rn(g.x, g.y);
    *(__half2*)(ff + i + 2) = __floats2half2_rn(g.z, g.w);
}

// ---------------------------------------------------------------------------
// Launch
// ---------------------------------------------------------------------------
extern "C" void kernel_launch(void* const* d_in, const int* in_sizes, int n_in,
                              void* d_out, int out_size)
{
    const float* x       = (const float*)d_in[0];
    const float* mask    = (const float*)d_in[1];
    const float* norm1_w = (const float*)d_in[2];
    const float* qkv_w   = (const float*)d_in[3];
    const float* out_w   = (const float*)d_in[4];
    const float* norm2_w = (const float*)d_in[5];
    const float* gate_w  = (const float*)d_in[6];
    const float* up_w    = (const float*)d_in[7];
    const float* down_w  = (const float*)d_in[8];
    float* out = (float*)d_out;

    __half *wqkv, *wout, *wgate, *wup, *wdown;
    __half *h1, *qkvh, *p16, *oh, *h2, *ff;
    float *scores, *x2, *gate, *up;
    cudaGetSymbolAddress((void**)&wqkv,  g_wqkv);
    cudaGetSymbolAddress((void**)&wout,  g_wout);
    cudaGetSymbolAddress((void**)&wgate, g_wgate);
    cudaGetSymbolAddress((void**)&wup,   g_wup);
    cudaGetSymbolAddress((void**)&wdown, g_wdown);
    cudaGetSymbolAddress((void**)&h1,    g_h1);
    cudaGetSymbolAddress((void**)&qkvh,  g_qkv);
    cudaGetSymbolAddress((void**)&scores,g_scores);
    cudaGetSymbolAddress((void**)&p16,   g_p);
    cudaGetSymbolAddress((void**)&oh,    g_o);
    cudaGetSymbolAddress((void**)&x2,    g_x2);
    cudaGetSymbolAddress((void**)&h2,    g_h2);
    cudaGetSymbolAddress((void**)&gate,  g_gate);
    cudaGetSymbolAddress((void**)&up,    g_up);
    cudaGetSymbolAddress((void**)&ff,    g_ff);

    cudaFuncSetAttribute(gemm_h<0, 0>, cudaFuncAttributeMaxDynamicSharedMemorySize, GEMM_SMEM);
    cudaFuncSetAttribute(gemm_h<0, 1>, cudaFuncAttributeMaxDynamicSharedMemorySize, GEMM_SMEM);
    cudaFuncSetAttribute(gemm_h<1, 0>, cudaFuncAttributeMaxDynamicSharedMemorySize, GEMM_SMEM);
    cudaFuncSetAttribute(attn_pv_h, cudaFuncAttributeMaxDynamicSharedMemorySize, PV_SMEM);

    // 0. convert weights to fp16
    f2h_kernel<<<(unsigned)((size_t)QKVD * DD / 1024), 256>>>(qkv_w, wqkv);
    f2h_kernel<<<(unsigned)((size_t)DD * DD / 1024), 256>>>(out_w, wout);
    f2h_kernel<<<(unsigned)((size_t)FF_ * DD / 1024), 256>>>(gate_w, wgate);
    f2h_kernel<<<(unsigned)((size_t)FF_ * DD / 1024), 256>>>(up_w, wup);
    f2h_kernel<<<(unsigned)((size_t)DD * FF_ / 1024), 256>>>(down_w, wdown);

    // 1. h1 = rmsnorm(x) (fp16 out)
    rmsnorm_h<<<RR, 256>>>(x, norm1_w, h1);

    // 2. qkv = h1 @ qkv_w^T (fp16 out)
    gemm_h<1, 0><<<dim3(QKVD / 128, RR / 128), 256, GEMM_SMEM>>>(
        h1, wqkv, nullptr, qkvh, QKVD, DD);

    // 3. scores (causal tiles only)
    attn_scores_h<<<dim3(LL / 128, LL / 128, BB * HH), 256, SC_SMEM>>>(
        qkvh, mask, scores);

    // 4. causal softmax -> fp16 P
    softmax_causal<<<BB * HH * LL, 256>>>(scores, p16);

    // 5. O = P @ V (fp16 out, (b,l,h,d) layout)
    attn_pv_h<<<dim3(LL / 128, BB * HH), 256, PV_SMEM>>>(qkvh, p16, oh);

    // 6. x2 = x + O @ out_w^T (fp32)
    gemm_h<0, 1><<<dim3(DD / 128, RR / 128), 256, GEMM_SMEM>>>(
        oh, wout, x, x2, DD, DD);

    // 7. h2 = rmsnorm(x2) (fp16)
    rmsnorm_h<<<RR, 256>>>(x2, norm2_w, h2);

    // 8. gate/up projections (fp32 out for silu precision)
    gemm_h<0, 0><<<dim3(FF_ / 128, RR / 128), 256, GEMM_SMEM>>>(
        h2, wgate, nullptr, gate, FF_, DD);
    gemm_h<0, 0><<<dim3(FF_ / 128, RR / 128), 256, GEMM_SMEM>>>(
        h2, wup, nullptr, up, FF_, DD);

    // 9. ff = silu(gate)*up (fp16)
    silu_mul_h<<<(unsigned)(((size_t)RR * FF_) / 1024), 256>>>(gate, up, ff);

    // 10. out = x2 + ff @ down_w^T (fp32)
    gemm_h<0, 1><<<dim3(DD / 128, RR / 128), 256, GEMM_SMEM>>>(
        ff, wdown, x2, out, DD, FF_);
}